// round 2
// baseline (speedup 1.0000x reference)
#include <cuda_runtime.h>

#define EPS 1e-7f
#define BB 16
#define LL 1024
#define DD 256
#define PP 20

// ---------------- scratch (static __device__, no allocation) ----------------
__device__ float g_inv1[BB*LL];          // 1/n1
__device__ float g_inv2[BB*LL];          // 1/n2
__device__ float g_Mpart[4*BB*DD*DD];    // m-split partial Gram matrices (16 MB)
__device__ float g_vpart[4*BB*DD];       // m-split partial v
__device__ float g_M[BB*DD*DD];          // reduced Gram (4 MB)
__device__ float g_v[BB*DD];             // reduced v
__device__ float g_w[BB*LL*DD];          // weighted = x1 @ M (16 MB)

// ---------------- K0: per-row inverse norms (warp per row) ----------------
__global__ __launch_bounds__(256) void k_norms(const float* __restrict__ s1,
                                               const float* __restrict__ s2) {
    int gw   = (blockIdx.x * 256 + threadIdx.x) >> 5;   // global warp id, 0..32767
    int lane = threadIdx.x & 31;
    const float* src; float* dst; int r;
    if (gw < BB*LL) { src = s1; dst = g_inv1; r = gw; }
    else            { src = s2; dst = g_inv2; r = gw - BB*LL; }
    const float4* p = reinterpret_cast<const float4*>(src) + (size_t)r * (DD/4);
    float4 a = p[lane];
    float4 b = p[lane + 32];
    float ss = a.x*a.x + a.y*a.y + a.z*a.z + a.w*a.w
             + b.x*b.x + b.y*b.y + b.z*b.z + b.w*b.w;
#pragma unroll
    for (int o = 16; o; o >>= 1) ss += __shfl_xor_sync(0xffffffffu, ss, o);
    if (lane == 0) dst[r] = rsqrtf(fmaxf(ss, EPS));
}

// ---------------- K1: Gram matrix M[b] = s2^T diag(1/n2) s2 (m-split x4) ----
// grid (b=16, jt=4, ms=4); block 256. Tile: 256 i-rows x 64 j-cols, 8x8 regs/thread.
__global__ __launch_bounds__(256) void k_gram(const float* __restrict__ s2) {
    __shared__ float sRaw[16][256];   // raw s2 chunk [m][d]
    __shared__ float sScl[16][64];    // y2 chunk restricted to this j-tile
    __shared__ float sInv[16];
    int b = blockIdx.x, jt = blockIdx.y, ms = blockIdx.z;
    int j0 = jt * 64;
    int m0 = ms * 256;
    int tid = threadIdx.x;
    int ig = tid >> 3;      // 0..31 -> i rows ig*8..ig*8+7
    int jg = tid & 7;       // 0..7  -> j cols j0+jg*8..+7
    float acc[8][8];
#pragma unroll
    for (int i = 0; i < 8; i++)
#pragma unroll
        for (int j = 0; j < 8; j++) acc[i][j] = 0.f;
    float vreg = 0.f;
    const float* base = s2 + (size_t)b * LL * DD;

    for (int c = 0; c < 16; c++) {              // 16 chunks of MC=16 m-rows
        int mb = m0 + c * 16;
        __syncthreads();
        const float4* src = reinterpret_cast<const float4*>(base + (size_t)mb * DD);
#pragma unroll
        for (int t = 0; t < 4; t++) {
            int f4 = tid + t * 256;             // 0..1023
            int row = f4 >> 6, c4 = f4 & 63;
            reinterpret_cast<float4*>(&sRaw[row][0])[c4] = src[row * 64 + c4];
        }
        if (tid < 16) sInv[tid] = g_inv2[b * LL + mb + tid];
        __syncthreads();
#pragma unroll
        for (int t = 0; t < 4; t++) {
            int idx = tid + t * 256;            // 0..1023 over 16x64
            int row = idx >> 6, col = idx & 63;
            sScl[row][col] = sRaw[row][j0 + col] * sInv[row];
        }
        __syncthreads();
        if (tid < 64) {
#pragma unroll
            for (int m = 0; m < 16; m++) vreg += sScl[m][tid];
        }
#pragma unroll 4
        for (int m = 0; m < 16; m++) {
            float a[8], bb[8];
            *(float4*)&a[0]  = *(const float4*)&sRaw[m][ig * 8];
            *(float4*)&a[4]  = *(const float4*)&sRaw[m][ig * 8 + 4];
            *(float4*)&bb[0] = *(const float4*)&sScl[m][jg * 8];
            *(float4*)&bb[4] = *(const float4*)&sScl[m][jg * 8 + 4];
#pragma unroll
            for (int i = 0; i < 8; i++)
#pragma unroll
                for (int j = 0; j < 8; j++) acc[i][j] += a[i] * bb[j];
        }
    }

    float* dst = g_Mpart + ((size_t)ms * BB + b) * DD * DD;
#pragma unroll
    for (int i = 0; i < 8; i++) {
        int row = ig * 8 + i;
        *(float4*)&dst[row * DD + j0 + jg * 8]     = make_float4(acc[i][0], acc[i][1], acc[i][2], acc[i][3]);
        *(float4*)&dst[row * DD + j0 + jg * 8 + 4] = make_float4(acc[i][4], acc[i][5], acc[i][6], acc[i][7]);
    }
    if (tid < 64) g_vpart[((size_t)ms * BB + b) * DD + j0 + tid] = vreg;
}

// ---------------- K1b: reduce the 4 m-split partials ----------------
__global__ __launch_bounds__(256) void k_reduce() {
    int idx = blockIdx.x * 256 + threadIdx.x;
    const int MF4 = BB * DD * DD / 4;           // 262144 float4 per part
    if (idx < MF4) {
        const float4* p = reinterpret_cast<const float4*>(g_Mpart);
        float4 a = p[idx], b = p[idx + MF4], c = p[idx + 2*MF4], d = p[idx + 3*MF4];
        float4 s = make_float4(a.x+b.x+c.x+d.x, a.y+b.y+c.y+d.y,
                               a.z+b.z+c.z+d.z, a.w+b.w+c.w+d.w);
        reinterpret_cast<float4*>(g_M)[idx] = s;
    } else {
        int r = idx - MF4;
        const int VN = BB * DD;                  // 4096
        if (r < VN)
            g_v[r] = g_vpart[r] + g_vpart[r+VN] + g_vpart[r+2*VN] + g_vpart[r+3*VN];
    }
}

// ---------------- K2: weighted = x1 @ M[b] ----------------
// grid (b=16, lt=16); block 256. Tile: 64 l-rows x 256 j-cols, 8x8 regs/thread.
__global__ __launch_bounds__(256) void k_weighted(const float* __restrict__ s1) {
    __shared__ float sX[64][33];      // x1 tile [l][k], +1 pad: conflict-free staging
    __shared__ float sM[32][256];     // M chunk [k][j]
    int b = blockIdx.x, lt = blockIdx.y;
    int l0 = lt * 64;
    int tid = threadIdx.x;
    int lg = tid >> 5;    // 0..7  -> l rows lg*8..+7
    int jg = tid & 31;    // 0..31 -> j cols jg*8..+7
    float acc[8][8];
#pragma unroll
    for (int i = 0; i < 8; i++)
#pragma unroll
        for (int j = 0; j < 8; j++) acc[i][j] = 0.f;

    for (int c = 0; c < 8; c++) {               // 8 chunks of KC=32 over d
        int k0 = c * 32;
        __syncthreads();
#pragma unroll
        for (int t = 0; t < 2; t++) {
            int f4 = tid + t * 256;             // 0..511 over 64 rows x 8 f4
            int row = f4 >> 3, c4 = f4 & 7;
            float4 v = *reinterpret_cast<const float4*>(
                s1 + ((size_t)(b * LL + l0 + row)) * DD + k0 + c4 * 4);
            float inv = g_inv1[b * LL + l0 + row];
            sX[row][c4*4+0] = v.x * inv;
            sX[row][c4*4+1] = v.y * inv;
            sX[row][c4*4+2] = v.z * inv;
            sX[row][c4*4+3] = v.w * inv;
        }
        const float4* msrc = reinterpret_cast<const float4*>(
            g_M + (size_t)b * DD * DD + (size_t)k0 * DD);
#pragma unroll
        for (int t = 0; t < 8; t++) {
            int f4 = tid + t * 256;             // 0..2047 over 32x256
            reinterpret_cast<float4*>(&sM[0][0])[f4] = msrc[f4];
        }
        __syncthreads();
#pragma unroll 4
        for (int k = 0; k < 32; k++) {
            float a[8], bb[8];
#pragma unroll
            for (int i = 0; i < 8; i++) a[i] = sX[lg * 8 + i][k];   // broadcast LDS
            *(float4*)&bb[0] = *(const float4*)&sM[k][jg * 8];
            *(float4*)&bb[4] = *(const float4*)&sM[k][jg * 8 + 4];
#pragma unroll
            for (int i = 0; i < 8; i++)
#pragma unroll
                for (int j = 0; j < 8; j++) acc[i][j] += a[i] * bb[j];
        }
    }

    float* dst = g_w + ((size_t)(b * LL + l0)) * DD;
#pragma unroll
    for (int i = 0; i < 8; i++) {
        int row = lg * 8 + i;
        *(float4*)&dst[row * DD + jg * 8]     = make_float4(acc[i][0], acc[i][1], acc[i][2], acc[i][3]);
        *(float4*)&dst[row * DD + jg * 8 + 4] = make_float4(acc[i][4], acc[i][5], acc[i][6], acc[i][7]);
    }
}

// ---------------- K3: epilogue — mav, perspective cosines (warp per row) ----
__global__ __launch_bounds__(256) void k_out(const float* __restrict__ s1,
                                             const float* __restrict__ ker,
                                             float* __restrict__ out) {
    __shared__ float ksq[PP * DD];    // kernel^2, 20 KB
    __shared__ float vsh[DD];
    __shared__ float obuf[8][PP];
    int tid = threadIdx.x;
    int row0 = blockIdx.x * 8;
    int b = row0 >> 10;
    for (int i = tid; i < PP * DD; i += 256) { float t = ker[i]; ksq[i] = t * t; }
    vsh[tid] = g_v[b * DD + tid];
    __syncthreads();

    int w = tid >> 5, lane = tid & 31;
    int row = row0 + w;
    const float4* ap = reinterpret_cast<const float4*>(s1) + (size_t)row * 64;
    float4 A0 = ap[lane * 2], A1 = ap[lane * 2 + 1];
    const float4* wp = reinterpret_cast<const float4*>(g_w) + (size_t)row * 64;
    float4 W0 = wp[lane * 2], W1 = wp[lane * 2 + 1];
    float s[8]  = {A0.x, A0.y, A0.z, A0.w, A1.x, A1.y, A1.z, A1.w};
    float wv[8] = {W0.x, W0.y, W0.z, W0.w, W1.x, W1.y, W1.z, W1.w};

    // rowsum(cos) = inv_n1 * (s1 . v)
    float rs = 0.f;
    const float* vp = &vsh[lane * 8];
#pragma unroll
    for (int i = 0; i < 8; i++) rs += s[i] * vp[i];
#pragma unroll
    for (int o = 16; o; o >>= 1) rs += __shfl_xor_sync(0xffffffffu, rs, o);
    float denom = g_inv1[row] * rs + EPS;
    float invd = 1.0f / denom;

    float mv[8], sm[8], ssq[8], msq[8];
#pragma unroll
    for (int i = 0; i < 8; i++) {
        mv[i]  = wv[i] * invd;
        sm[i]  = s[i] * mv[i];
        ssq[i] = s[i] * s[i];
        msq[i] = mv[i] * mv[i];
    }

    for (int p = 0; p < PP; p++) {
        const float* kp = &ksq[p * DD + lane * 8];
        float4 K0 = *(const float4*)kp;
        float4 K1 = *(const float4*)(kp + 4);
        float kk[8] = {K0.x, K0.y, K0.z, K0.w, K1.x, K1.y, K1.z, K1.w};
        float n = 0.f, d1 = 0.f, d2 = 0.f;
#pragma unroll
        for (int i = 0; i < 8; i++) {
            n  += kk[i] * sm[i];
            d1 += kk[i] * ssq[i];
            d2 += kk[i] * msq[i];
        }
#pragma unroll
        for (int o = 16; o; o >>= 1) {
            n  += __shfl_xor_sync(0xffffffffu, n,  o);
            d1 += __shfl_xor_sync(0xffffffffu, d1, o);
            d2 += __shfl_xor_sync(0xffffffffu, d2, o);
        }
        if (lane == 0)
            obuf[w][p] = n * rsqrtf(fmaxf(d1, EPS)) * rsqrtf(fmaxf(d2, EPS));
    }
    __syncwarp();
    if (lane < PP) out[(size_t)row * PP + lane] = obuf[w][lane];
}

// ---------------- launch ----------------
extern "C" void kernel_launch(void* const* d_in, const int* in_sizes, int n_in,
                              void* d_out, int out_size) {
    const float* s1  = (const float*)d_in[0];   // [16,1024,256]
    const float* s2  = (const float*)d_in[1];   // [16,1024,256]
    const float* ker = (const float*)d_in[2];   // [20,256]
    float* out = (float*)d_out;                 // [16,1024,20]

    k_norms<<<4096, 256>>>(s1, s2);
    dim3 g1(16, 4, 4);
    k_gram<<<g1, 256>>>(s2);
    k_reduce<<<1040, 256>>>();
    dim3 g2(16, 16);
    k_weighted<<<g2, 256>>>(s1);
    k_out<<<2048, 256>>>(s1, ker, out);
}